// round 1
// baseline (speedup 1.0000x reference)
#include <cuda_runtime.h>
#include <math.h>

#define B_  8
#define S_  512
#define D_  1024
#define H_  16
#define DH_ 64
#define BH_ (B_*H_)

// ---------------- scratch (device globals; no runtime allocation) ----------------
__device__ float g_qh[(size_t)BH_*S_*DH_];   // [B,H,S,DH]
__device__ float g_kh[(size_t)BH_*S_*DH_];
__device__ float g_vh[(size_t)BH_*S_*DH_];
__device__ float g_sc[(size_t)BH_*S_*S_];    // scores -> probs  (134 MB)
__device__ float g_att[(size_t)B_*S_*D_];    // attention out in concat layout [B,S,H*DH]

// ---------------------------------------------------------------------------------
// GEMM: C = A[M,K] * W[N,K]^T + bias.  M=4096, N=K=1024.
// HEADOUT=true  -> write to [B,H,S,DH] head layout (projection kernels)
// HEADOUT=false -> write row-major [M,N] (output projection)
// BM=BN=128, BK=16, TM=TN=8, 256 threads.
// ---------------------------------------------------------------------------------
template<bool HEADOUT>
__global__ __launch_bounds__(256)
void gemm_nt(const float* __restrict__ A, const float* __restrict__ W,
             const float* __restrict__ bias, float* __restrict__ out)
{
    constexpr int BM = 128, BN = 128, BK = 16, TM = 8, TN = 8;
    const int K = D_;
    __shared__ float As[BK][BM];
    __shared__ float Bs[BK][BN];

    int tid = threadIdx.x;
    int m0 = blockIdx.y * BM, n0 = blockIdx.x * BN;
    int tx = tid % (BN / TN);          // 0..15
    int ty = tid / (BN / TN);          // 0..15

    float acc[TM][TN];
    #pragma unroll
    for (int u = 0; u < TM; u++)
        #pragma unroll
        for (int w = 0; w < TN; w++) acc[u][w] = 0.f;

    for (int k0 = 0; k0 < K; k0 += BK) {
        // load A tile (BM x BK) transposed into As[k][m]; 512 float4 total
        #pragma unroll
        for (int r = 0; r < 2; r++) {
            int id = tid + r * 256;            // 0..511
            int m  = id >> 2;                  // /4 -> 0..127
            int kq = (id & 3) * 4;             // 0,4,8,12
            float4 vv = *(const float4*)(A + (size_t)(m0 + m) * K + k0 + kq);
            As[kq+0][m] = vv.x; As[kq+1][m] = vv.y;
            As[kq+2][m] = vv.z; As[kq+3][m] = vv.w;
        }
        // load B tile (BN x BK of W, rows are output features) into Bs[k][n]
        #pragma unroll
        for (int r = 0; r < 2; r++) {
            int id = tid + r * 256;
            int n  = id >> 2;
            int kq = (id & 3) * 4;
            float4 vv = *(const float4*)(W + (size_t)(n0 + n) * K + k0 + kq);
            Bs[kq+0][n] = vv.x; Bs[kq+1][n] = vv.y;
            Bs[kq+2][n] = vv.z; Bs[kq+3][n] = vv.w;
        }
        __syncthreads();

        #pragma unroll
        for (int k = 0; k < BK; k++) {
            float a[TM], b[TN];
            float4 a0 = *(const float4*)&As[k][ty*TM];
            float4 a1 = *(const float4*)&As[k][ty*TM+4];
            a[0]=a0.x; a[1]=a0.y; a[2]=a0.z; a[3]=a0.w;
            a[4]=a1.x; a[5]=a1.y; a[6]=a1.z; a[7]=a1.w;
            float4 b0 = *(const float4*)&Bs[k][tx*TN];
            float4 b1 = *(const float4*)&Bs[k][tx*TN+4];
            b[0]=b0.x; b[1]=b0.y; b[2]=b0.z; b[3]=b0.w;
            b[4]=b1.x; b[5]=b1.y; b[6]=b1.z; b[7]=b1.w;
            #pragma unroll
            for (int u = 0; u < TM; u++)
                #pragma unroll
                for (int w = 0; w < TN; w++) acc[u][w] += a[u] * b[w];
        }
        __syncthreads();
    }

    #pragma unroll
    for (int u = 0; u < TM; u++) {
        int m = m0 + ty * TM + u;
        int bb = m / S_, s = m % S_;
        #pragma unroll
        for (int w = 0; w < TN; w++) {
            int n = n0 + tx * TN + w;
            float val = acc[u][w] + bias[n];
            if (HEADOUT) {
                int h = n / DH_, d = n % DH_;
                g_qh[0]; // keep template instantiation honest (no-op)
                out[(((size_t)bb * H_ + h) * S_ + s) * DH_ + d] = val;
            } else {
                out[(size_t)m * D_ + n] = val;
            }
        }
    }
}

// ---------------------------------------------------------------------------------
// Scores: per head z, C[i,j] = dot(qh[i], kh[j]) / 8.  M=N=512, K=64.
// Causal: skip tiles entirely above the diagonal.
// BM=BN=64, BK=16, TM=TN=4, 256 threads.
// ---------------------------------------------------------------------------------
__global__ __launch_bounds__(256)
void scores_kernel()
{
    constexpr int BM = 64, BN = 64, BK = 16, TM = 4, TN = 4;
    int z  = blockIdx.z;
    int m0 = blockIdx.y * BM, n0 = blockIdx.x * BN;
    if (n0 > m0) return;   // tile entirely above causal diagonal

    const float* Q  = g_qh + (size_t)z * S_ * DH_;
    const float* Kh = g_kh + (size_t)z * S_ * DH_;
    float*       C  = g_sc + (size_t)z * S_ * S_;

    __shared__ float As[BK][BM];
    __shared__ float Bs[BK][BN];

    int tid = threadIdx.x;
    int tx = tid % (BN / TN);   // 0..15
    int ty = tid / (BN / TN);   // 0..15

    float acc[TM][TN];
    #pragma unroll
    for (int u = 0; u < TM; u++)
        #pragma unroll
        for (int w = 0; w < TN; w++) acc[u][w] = 0.f;

    for (int k0 = 0; k0 < DH_; k0 += BK) {
        // A tile: 64x16 = 256 float4, 1 per thread
        {
            int m  = tid >> 2;
            int kq = (tid & 3) * 4;
            float4 vv = *(const float4*)(Q + (size_t)(m0 + m) * DH_ + k0 + kq);
            As[kq+0][m] = vv.x; As[kq+1][m] = vv.y;
            As[kq+2][m] = vv.z; As[kq+3][m] = vv.w;
        }
        {
            int n  = tid >> 2;
            int kq = (tid & 3) * 4;
            float4 vv = *(const float4*)(Kh + (size_t)(n0 + n) * DH_ + k0 + kq);
            Bs[kq+0][n] = vv.x; Bs[kq+1][n] = vv.y;
            Bs[kq+2][n] = vv.z; Bs[kq+3][n] = vv.w;
        }
        __syncthreads();
        #pragma unroll
        for (int k = 0; k < BK; k++) {
            float a[TM], b[TN];
            float4 a0 = *(const float4*)&As[k][ty*TM];
            a[0]=a0.x; a[1]=a0.y; a[2]=a0.z; a[3]=a0.w;
            float4 b0 = *(const float4*)&Bs[k][tx*TN];
            b[0]=b0.x; b[1]=b0.y; b[2]=b0.z; b[3]=b0.w;
            #pragma unroll
            for (int u = 0; u < TM; u++)
                #pragma unroll
                for (int w = 0; w < TN; w++) acc[u][w] += a[u] * b[w];
        }
        __syncthreads();
    }

    #pragma unroll
    for (int u = 0; u < TM; u++) {
        int i = m0 + ty * TM + u;
        #pragma unroll
        for (int w = 0; w < TN; w++) {
            int j = n0 + tx * TN + w;
            C[(size_t)i * S_ + j] = acc[u][w] * 0.125f;  // 1/sqrt(64)
        }
    }
}

// ---------------------------------------------------------------------------------
// Per-row: softmax -> cumsum -> distance decay -> reweight -> softmax -> zero row 0.
// One 512-thread block per (b,h,i) row; thread j handles key position j.
// ---------------------------------------------------------------------------------
__global__ __launch_bounds__(S_)
void row_kernel(const float* __restrict__ pdiff, const float* __restrict__ gammas)
{
    int i = blockIdx.x;
    int z = blockIdx.y;            // b*H + h
    int b = z / H_, h = z % H_;
    int j = threadIdx.x;

    float* row = g_sc + ((size_t)z * S_ + i) * S_;
    bool valid = (j <= i);
    float sc = valid ? row[j] : 0.f;

    __shared__ float sh[S_];

    // ---- first softmax: max ----
    sh[j] = valid ? sc : -3.0e38f;
    __syncthreads();
    #pragma unroll
    for (int off = S_/2; off > 0; off >>= 1) {
        if (j < off) sh[j] = fmaxf(sh[j], sh[j + off]);
        __syncthreads();
    }
    float m1 = sh[0];
    __syncthreads();

    float p = valid ? __expf(sc - m1) : 0.f;

    // ---- inclusive scan (Hillis-Steele) ----
    sh[j] = p;
    __syncthreads();
    #pragma unroll
    for (int off = 1; off < S_; off <<= 1) {
        float v = (j >= off) ? sh[j - off] : 0.f;
        __syncthreads();
        sh[j] += v;
        __syncthreads();
    }
    float cum = sh[j];
    float tot = sh[S_ - 1];
    __syncthreads();

    // remaining (normalized) probability mass strictly after j
    float rem = fmaxf(tot - cum, 0.f) / fmaxf(tot, 1e-30f);
    float pos = fabsf((float)(i - j));
    float dist = sqrtf(fmaxf(rem * pos, 0.f));

    float g  = gammas[h];
    float sp = (g > 20.f) ? g : log1pf(__expf(g));
    float gamma = -sp;

    float pd  = pdiff[((size_t)b * S_ + i) * S_ + j];
    float sig = 1.f / (1.f + __expf(-pd));
    float dv  = __expf(sig);

    float eff = __expf(dist * gamma * dv);
    eff = fminf(fmaxf(eff, 1e-5f), 1e5f);

    float s2 = sc * eff;

    // ---- second softmax ----
    sh[j] = valid ? s2 : -3.0e38f;
    __syncthreads();
    #pragma unroll
    for (int off = S_/2; off > 0; off >>= 1) {
        if (j < off) sh[j] = fmaxf(sh[j], sh[j + off]);
        __syncthreads();
    }
    float m2 = sh[0];
    __syncthreads();

    float e2 = valid ? __expf(s2 - m2) : 0.f;
    sh[j] = e2;
    __syncthreads();
    #pragma unroll
    for (int off = S_/2; off > 0; off >>= 1) {
        if (j < off) sh[j] += sh[j + off];
        __syncthreads();
    }
    float t2 = sh[0];

    float outp = (i == 0) ? 0.f : (valid ? e2 / t2 : 0.f);
    row[j] = outp;   // full row written (zeros above diagonal) so PV GEMM is dense
}

// ---------------------------------------------------------------------------------
// PV: per head z, out[i,d] = sum_j P[i,j] * V[j,d].  M=512, N=64, K<=512 (causal).
// Writes directly into concat layout g_att[b, i, h*DH+d].
// ---------------------------------------------------------------------------------
__global__ __launch_bounds__(256)
void pv_kernel()
{
    constexpr int BM = 64, BN = 64, BK = 16, TM = 4, TN = 4;
    int z  = blockIdx.z;
    int b  = z / H_, h = z % H_;
    int m0 = blockIdx.y * BM;

    const float* P = g_sc + (size_t)z * S_ * S_;
    const float* V = g_vh + (size_t)z * S_ * DH_;

    __shared__ float As[BK][BM];
    __shared__ float Bs[BK][BN];

    int tid = threadIdx.x;
    int tx = tid % (BN / TN);
    int ty = tid / (BN / TN);

    float acc[TM][TN];
    #pragma unroll
    for (int u = 0; u < TM; u++)
        #pragma unroll
        for (int w = 0; w < TN; w++) acc[u][w] = 0.f;

    int kmax = m0 + BM;   // causal: P[i,j]==0 for j>i; block max i = m0+63
    if (kmax > S_) kmax = S_;

    for (int k0 = 0; k0 < kmax; k0 += BK) {
        // A tile: P rows (64x16), 256 float4
        {
            int m  = tid >> 2;
            int kq = (tid & 3) * 4;
            float4 vv = *(const float4*)(P + (size_t)(m0 + m) * S_ + k0 + kq);
            As[kq+0][m] = vv.x; As[kq+1][m] = vv.y;
            As[kq+2][m] = vv.z; As[kq+3][m] = vv.w;
        }
        // B tile: V[k, n] (16x64), coalesced along n
        {
            int k  = tid >> 4;             // 0..15
            int nq = (tid & 15) * 4;       // 0..60
            float4 vv = *(const float4*)(V + (size_t)(k0 + k) * DH_ + nq);
            Bs[k][nq+0] = vv.x; Bs[k][nq+1] = vv.y;
            Bs[k][nq+2] = vv.z; Bs[k][nq+3] = vv.w;
        }
        __syncthreads();
        #pragma unroll
        for (int k = 0; k < BK; k++) {
            float a[TM], bb[TN];
            float4 a0 = *(const float4*)&As[k][ty*TM];
            a[0]=a0.x; a[1]=a0.y; a[2]=a0.z; a[3]=a0.w;
            float4 b0 = *(const float4*)&Bs[k][tx*TN];
            bb[0]=b0.x; bb[1]=b0.y; bb[2]=b0.z; bb[3]=b0.w;
            #pragma unroll
            for (int u = 0; u < TM; u++)
                #pragma unroll
                for (int w = 0; w < TN; w++) acc[u][w] += a[u] * bb[w];
        }
        __syncthreads();
    }

    #pragma unroll
    for (int u = 0; u < TM; u++) {
        int i = m0 + ty * TM + u;
        #pragma unroll
        for (int w = 0; w < TN; w++) {
            int d = tx * TN + w;
            g_att[((size_t)b * S_ + i) * D_ + h * DH_ + d] = acc[u][w];
        }
    }
}

// ---------------------------------------------------------------------------------
extern "C" void kernel_launch(void* const* d_in, const int* in_sizes, int n_in,
                              void* d_out, int out_size)
{
    const float* q      = (const float*)d_in[0];
    const float* k      = (const float*)d_in[1];
    const float* v      = (const float*)d_in[2];
    const float* pdiff  = (const float*)d_in[3];
    const float* Wk     = (const float*)d_in[4];
    const float* bk     = (const float*)d_in[5];
    const float* Wv     = (const float*)d_in[6];
    const float* bv     = (const float*)d_in[7];
    const float* Wo     = (const float*)d_in[8];
    const float* bo     = (const float*)d_in[9];
    const float* gammas = (const float*)d_in[10];
    float* out = (float*)d_out;

    float *qh, *kh, *vh, *att;
    cudaGetSymbolAddress((void**)&qh,  g_qh);
    cudaGetSymbolAddress((void**)&kh,  g_kh);
    cudaGetSymbolAddress((void**)&vh,  g_vh);
    cudaGetSymbolAddress((void**)&att, g_att);

    dim3 gproj(D_ / 128, (B_ * S_) / 128);   // (8, 32)

    gemm_nt<true><<<gproj, 256>>>(q, Wk, bk, qh);
    gemm_nt<true><<<gproj, 256>>>(k, Wk, bk, kh);
    gemm_nt<true><<<gproj, 256>>>(v, Wv, bv, vh);

    scores_kernel<<<dim3(8, 8, BH_), 256>>>();

    row_kernel<<<dim3(S_, BH_), S_>>>(pdiff, gammas);

    pv_kernel<<<dim3(1, 8, BH_), 256>>>();

    gemm_nt<false><<<gproj, 256>>>(att, Wo, bo, out);
}

// round 3
// speedup vs baseline: 2.5389x; 2.5389x over previous
#include <cuda_runtime.h>
#include <cuda_bf16.h>
#include <math.h>
#include <stdint.h>

#define B_  8
#define S_  512
#define D_  1024
#define H_  16
#define DH_ 64
#define BH_ (B_*H_)

// ---------------- scratch (device globals; no runtime allocation) ----------------
__device__ float g_qh[(size_t)BH_*S_*DH_];   // [B,H,S,DH]
__device__ float g_kh[(size_t)BH_*S_*DH_];
__device__ float g_vh[(size_t)BH_*S_*DH_];
__device__ float g_sc[(size_t)BH_*S_*S_];    // scores -> probs
__device__ float g_att[(size_t)B_*S_*D_];    // attention out, concat layout [B,S,D]
__device__ float g_dv[(size_t)B_*S_*S_];     // exp(sigmoid(pdiff)), shared across heads

// ======================= warp-level bf16 MMA (HMMA, no 'a'-gate) ==================
__device__ __forceinline__ void mma_bf16(float* c, uint32_t a0, uint32_t a1,
                                         uint32_t a2, uint32_t a3,
                                         uint32_t b0, uint32_t b1) {
    asm volatile(
        "mma.sync.aligned.m16n8k16.row.col.f32.bf16.bf16.f32 "
        "{%0,%1,%2,%3}, {%4,%5,%6,%7}, {%8,%9}, {%0,%1,%2,%3};"
        : "+f"(c[0]), "+f"(c[1]), "+f"(c[2]), "+f"(c[3])
        : "r"(a0), "r"(a1), "r"(a2), "r"(a3), "r"(b0), "r"(b1));
}

__device__ __forceinline__ uint32_t pack_bf16(float x, float y) {
    __nv_bfloat162 t = __floats2bfloat162_rn(x, y);
    return *(uint32_t*)&t;
}

// ==================================================================================
// Tensor-core GEMM (bf16x3 fp32 emulation):  C = A[M,K] * W[N,K]^T + bias
// M=4096, N=K=1024.  Block 128x128, BK=32, 8 warps (2x4), warp tile 64x32.
// 3 MMA passes per fragment: Ahi*Bhi + Ahi*Blo + Alo*Bhi  (fp32 accumulate).
// SMEM rows padded to 40 bf16 (20 words) -> conflict-free fragment LDS.
// ==================================================================================
#define PAD_W 20   // words per SMEM row (40 bf16, data uses 32)

template<bool HEADOUT>
__global__ __launch_bounds__(256, 1)
void gemm_mma(const float* __restrict__ A, const float* __restrict__ W,
              const float* __restrict__ bias, float* __restrict__ out)
{
    __shared__ uint32_t sAh[128 * PAD_W];
    __shared__ uint32_t sAl[128 * PAD_W];
    __shared__ uint32_t sBh[128 * PAD_W];
    __shared__ uint32_t sBl[128 * PAD_W];

    int tid = threadIdx.x, lane = tid & 31, wid = tid >> 5;
    int wm = wid >> 2, wn = wid & 3;          // warp grid 2 (M) x 4 (N)
    int m0 = blockIdx.y * 128, n0 = blockIdx.x * 128;
    int lq = lane >> 2, tq = lane & 3;        // groupID, threadID-in-group

    float acc[4][4][4];
    #pragma unroll
    for (int mt = 0; mt < 4; mt++)
        #pragma unroll
        for (int nt = 0; nt < 4; nt++)
            #pragma unroll
            for (int e = 0; e < 4; e++) acc[mt][nt][e] = 0.f;

    // staging-slot geometry: 1024 float4 per operand per chunk, 4 per thread
    int rowr[4], cqr[4], wofs[4];
    #pragma unroll
    for (int r = 0; r < 4; r++) {
        int g = tid + r * 256;
        rowr[r] = g >> 3;                      // 0..127
        cqr[r]  = g & 7;                       // float4 index within 32-col row
        wofs[r] = rowr[r] * PAD_W + cqr[r] * 2;
    }

    float4 va[4], vb[4];
    // prefetch chunk 0
    #pragma unroll
    for (int r = 0; r < 4; r++) {
        va[r] = *(const float4*)(A + (size_t)(m0 + rowr[r]) * D_ + cqr[r] * 4);
        vb[r] = *(const float4*)(W + (size_t)(n0 + rowr[r]) * D_ + cqr[r] * 4);
    }

    for (int kc = 0; kc < 32; kc++) {
        // ---- split fp32 -> bf16 hi/lo, store to padded SMEM ----
        #pragma unroll
        for (int r = 0; r < 4; r++) {
            float4 v = va[r];
            uint32_t h0 = pack_bf16(v.x, v.y);
            uint32_t h1 = pack_bf16(v.z, v.w);
            __nv_bfloat162 hh0 = *(__nv_bfloat162*)&h0;
            __nv_bfloat162 hh1 = *(__nv_bfloat162*)&h1;
            uint32_t l0 = pack_bf16(v.x - __bfloat162float(hh0.x),
                                    v.y - __bfloat162float(hh0.y));
            uint32_t l1 = pack_bf16(v.z - __bfloat162float(hh1.x),
                                    v.w - __bfloat162float(hh1.y));
            sAh[wofs[r]] = h0; sAh[wofs[r] + 1] = h1;
            sAl[wofs[r]] = l0; sAl[wofs[r] + 1] = l1;

            v = vb[r];
            h0 = pack_bf16(v.x, v.y);
            h1 = pack_bf16(v.z, v.w);
            hh0 = *(__nv_bfloat162*)&h0;
            hh1 = *(__nv_bfloat162*)&h1;
            l0 = pack_bf16(v.x - __bfloat162float(hh0.x),
                           v.y - __bfloat162float(hh0.y));
            l1 = pack_bf16(v.z - __bfloat162float(hh1.x),
                           v.w - __bfloat162float(hh1.y));
            sBh[wofs[r]] = h0; sBh[wofs[r] + 1] = h1;
            sBl[wofs[r]] = l0; sBl[wofs[r] + 1] = l1;
        }
        __syncthreads();

        // ---- prefetch next chunk (overlaps with MMA below) ----
        if (kc < 31) {
            int k0 = (kc + 1) * 32;
            #pragma unroll
            for (int r = 0; r < 4; r++) {
                va[r] = *(const float4*)(A + (size_t)(m0 + rowr[r]) * D_ + k0 + cqr[r] * 4);
                vb[r] = *(const float4*)(W + (size_t)(n0 + rowr[r]) * D_ + k0 + cqr[r] * 4);
            }
        }

        // ---- MMA: 2 k16-steps, warp tile 64x32, 3 hi/lo passes ----
        #pragma unroll
        for (int ks = 0; ks < 2; ks++) {
            int kofs = ks * 8 + tq;
            // B fragments for 4 n-tiles
            uint32_t bh[4][2], bl[4][2];
            #pragma unroll
            for (int nt = 0; nt < 4; nt++) {
                int bi = (wn * 32 + nt * 8 + lq) * PAD_W + kofs;
                bh[nt][0] = sBh[bi];     bh[nt][1] = sBh[bi + 4];
                bl[nt][0] = sBl[bi];     bl[nt][1] = sBl[bi + 4];
            }
            #pragma unroll
            for (int mt = 0; mt < 4; mt++) {
                int ai = (wm * 64 + mt * 16 + lq) * PAD_W + kofs;
                uint32_t ah0 = sAh[ai],               ah1 = sAh[ai + 8 * PAD_W];
                uint32_t ah2 = sAh[ai + 4],           ah3 = sAh[ai + 8 * PAD_W + 4];
                uint32_t al0 = sAl[ai],               al1 = sAl[ai + 8 * PAD_W];
                uint32_t al2 = sAl[ai + 4],           al3 = sAl[ai + 8 * PAD_W + 4];
                #pragma unroll
                for (int nt = 0; nt < 4; nt++) {
                    mma_bf16(acc[mt][nt], ah0, ah1, ah2, ah3, bh[nt][0], bh[nt][1]);
                    mma_bf16(acc[mt][nt], ah0, ah1, ah2, ah3, bl[nt][0], bl[nt][1]);
                    mma_bf16(acc[mt][nt], al0, al1, al2, al3, bh[nt][0], bh[nt][1]);
                }
            }
        }
        __syncthreads();
    }

    // ---- epilogue: add bias, store (fragment rows lq / lq+8, col pair tq*2) ----
    #pragma unroll
    for (int mt = 0; mt < 4; mt++) {
        #pragma unroll
        for (int nt = 0; nt < 4; nt++) {
            int n = n0 + wn * 32 + nt * 8 + tq * 2;
            float b0v = __ldg(bias + n), b1v = __ldg(bias + n + 1);
            #pragma unroll
            for (int half = 0; half < 2; half++) {
                int m = m0 + wm * 64 + mt * 16 + lq + half * 8;
                float v0 = acc[mt][nt][half * 2 + 0] + b0v;
                float v1 = acc[mt][nt][half * 2 + 1] + b1v;
                if (HEADOUT) {
                    int bb = m / S_, srow = m % S_;
                    int h = n >> 6, d = n & 63;
                    float2* p = (float2*)&out[(((size_t)bb * H_ + h) * S_ + srow) * DH_ + d];
                    *p = make_float2(v0, v1);
                } else {
                    float2* p = (float2*)&out[(size_t)m * D_ + n];
                    *p = make_float2(v0, v1);
                }
            }
        }
    }
}

// ==================================================================================
// Scores: per head z, C[i,j] = dot(qh[i], kh[j]) / 8.  fp32, causal tile skip.
// ==================================================================================
__global__ __launch_bounds__(256)
void scores_kernel()
{
    constexpr int BM = 64, BN = 64, BK = 16, TM = 4, TN = 4;
    int z  = blockIdx.z;
    int m0 = blockIdx.y * BM, n0 = blockIdx.x * BN;
    if (n0 > m0) return;

    const float* Q  = g_qh + (size_t)z * S_ * DH_;
    const float* Kh = g_kh + (size_t)z * S_ * DH_;
    float*       C  = g_sc + (size_t)z * S_ * S_;

    __shared__ float As[BK][BM];
    __shared__ float Bs[BK][BN];

    int tid = threadIdx.x;
    int tx = tid % (BN / TN);
    int ty = tid / (BN / TN);

    float acc[TM][TN];
    #pragma unroll
    for (int u = 0; u < TM; u++)
        #pragma unroll
        for (int w = 0; w < TN; w++) acc[u][w] = 0.f;

    for (int k0 = 0; k0 < DH_; k0 += BK) {
        {
            int m  = tid >> 2;
            int kq = (tid & 3) * 4;
            float4 vv = *(const float4*)(Q + (size_t)(m0 + m) * DH_ + k0 + kq);
            As[kq+0][m] = vv.x; As[kq+1][m] = vv.y;
            As[kq+2][m] = vv.z; As[kq+3][m] = vv.w;
        }
        {
            int n  = tid >> 2;
            int kq = (tid & 3) * 4;
            float4 vv = *(const float4*)(Kh + (size_t)(n0 + n) * DH_ + k0 + kq);
            Bs[kq+0][n] = vv.x; Bs[kq+1][n] = vv.y;
            Bs[kq+2][n] = vv.z; Bs[kq+3][n] = vv.w;
        }
        __syncthreads();
        #pragma unroll
        for (int k = 0; k < BK; k++) {
            float a[TM], b[TN];
            float4 a0 = *(const float4*)&As[k][ty*TM];
            a[0]=a0.x; a[1]=a0.y; a[2]=a0.z; a[3]=a0.w;
            float4 b0 = *(const float4*)&Bs[k][tx*TN];
            b[0]=b0.x; b[1]=b0.y; b[2]=b0.z; b[3]=b0.w;
            #pragma unroll
            for (int u = 0; u < TM; u++)
                #pragma unroll
                for (int w = 0; w < TN; w++) acc[u][w] += a[u] * b[w];
        }
        __syncthreads();
    }

    #pragma unroll
    for (int u = 0; u < TM; u++) {
        int i = m0 + ty * TM + u;
        #pragma unroll
        for (int w = 0; w < TN; w++) {
            int j = n0 + tx * TN + w;
            C[(size_t)i * S_ + j] = acc[u][w] * 0.125f;
        }
    }
}

// ==================================================================================
// dv precompute: dv[b,i,j] = exp(sigmoid(pdiff[b,i,j]))  (shared across all heads)
// ==================================================================================
__global__ __launch_bounds__(256)
void dv_kernel(const float* __restrict__ pdiff)
{
    size_t idx = (size_t)blockIdx.x * 256 + threadIdx.x;
    float x = pdiff[idx];
    float sig = 1.f / (1.f + __expf(-x));
    g_dv[idx] = __expf(sig);
}

// ==================================================================================
// Row kernel: warp per row, register-resident, shuffle scan, causal chunk skip.
// ==================================================================================
__global__ __launch_bounds__(256)
void row_kernel(const float* __restrict__ gammas)
{
    int warp = threadIdx.x >> 5, lane = threadIdx.x & 31;
    int i = blockIdx.x * 8 + warp;
    int z = blockIdx.y;               // b*H + h
    int b = z >> 4, h = z & 15;

    float* row = g_sc + ((size_t)z * S_ + i) * S_;
    const float* dvrow = g_dv + ((size_t)b * S_ + i) * S_;

    int nch = (i >> 5) + 1;
    float scv[16], s2v[16];

    float mx = -3.0e38f;
    #pragma unroll
    for (int c = 0; c < 16; c++) {
        if (c < nch) {
            int j = c * 32 + lane;
            float v = row[j];
            scv[c] = v;
            if (j <= i) mx = fmaxf(mx, v);
        }
    }
    #pragma unroll
    for (int o = 16; o > 0; o >>= 1) mx = fmaxf(mx, __shfl_xor_sync(0xFFFFFFFFu, mx, o));

    float run = 0.f;
    #pragma unroll
    for (int c = 0; c < 16; c++) {
        if (c < nch) {
            int j = c * 32 + lane;
            float p = (j <= i) ? __expf(scv[c] - mx) : 0.f;
            float s = p;
            #pragma unroll
            for (int d = 1; d < 32; d <<= 1) {
                float t = __shfl_up_sync(0xFFFFFFFFu, s, d);
                if (lane >= d) s += t;
            }
            s2v[c] = run + s;
            run += __shfl_sync(0xFFFFFFFFu, s, 31);
        }
    }
    float tot  = run;
    float rtot = 1.f / fmaxf(tot, 1e-30f);

    float g  = gammas[h];
    float gamma = -log1pf(__expf(g));

    float mx2 = -3.0e38f;
    #pragma unroll
    for (int c = 0; c < 16; c++) {
        if (c < nch) {
            int j = c * 32 + lane;
            float rem  = fmaxf(tot - s2v[c], 0.f) * rtot;
            float pos  = (float)(i - j);
            float dist = sqrtf(fmaxf(rem * pos, 0.f));
            float dv   = dvrow[j];
            float eff  = __expf(dist * gamma * dv);
            eff = fminf(fmaxf(eff, 1e-5f), 1e5f);
            float s2 = scv[c] * eff;
            s2v[c] = s2;
            if (j <= i) mx2 = fmaxf(mx2, s2);
        }
    }
    #pragma unroll
    for (int o = 16; o > 0; o >>= 1) mx2 = fmaxf(mx2, __shfl_xor_sync(0xFFFFFFFFu, mx2, o));

    float sum2 = 0.f;
    #pragma unroll
    for (int c = 0; c < 16; c++) {
        if (c < nch) {
            int j = c * 32 + lane;
            float e2 = (j <= i) ? __expf(s2v[c] - mx2) : 0.f;
            s2v[c] = e2;
            sum2 += e2;
        }
    }
    #pragma unroll
    for (int o = 16; o > 0; o >>= 1) sum2 += __shfl_xor_sync(0xFFFFFFFFu, sum2, o);

    float rs = (i == 0) ? 0.f : 1.f / sum2;

    int nwrite = ((i >> 6) + 1) * 2;
    #pragma unroll
    for (int c = 0; c < 16; c++) {
        int j = c * 32 + lane;
        if (c < nch)          row[j] = (j <= i) ? s2v[c] * rs : 0.f;
        else if (c < nwrite)  row[j] = 0.f;
    }
}

// ==================================================================================
// PV: per head z, out[i,d] = sum_j P[i,j] * V[j,d]. Causal-truncated K loop.
// ==================================================================================
__global__ __launch_bounds__(256)
void pv_kernel()
{
    constexpr int BM = 64, BN = 64, BK = 16, TM = 4, TN = 4;
    int z  = blockIdx.z;
    int b  = z / H_, h = z % H_;
    int m0 = blockIdx.y * BM;

    const float* P = g_sc + (size_t)z * S_ * S_;
    const float* V = g_vh + (size_t)z * S_ * DH_;

    __shared__ float As[BK][BM];
    __shared__ float Bs[BK][BN];

    int tid = threadIdx.x;
    int tx = tid % (BN / TN);
    int ty = tid / (BN / TN);

    float acc[TM][TN];
    #pragma unroll
    for (int u = 0; u < TM; u++)
        #pragma unroll
        for (int w = 0; w < TN; w++) acc[u][w] = 0.f;

    int kmax = m0 + BM;
    if (kmax > S_) kmax = S_;

    for (int k0 = 0; k0 < kmax; k0 += BK) {
        {
            int m  = tid >> 2;
            int kq = (tid & 3) * 4;
            float4 vv = *(const float4*)(P + (size_t)(m0 + m) * S_ + k0 + kq);
            As[kq+0][m] = vv.x; As[kq+1][m] = vv.y;
            As[kq+2][m] = vv.z; As[kq+3][m] = vv.w;
        }
        {
            int k  = tid >> 4;
            int nq = (tid & 15) * 4;
            float4 vv = *(const float4*)(V + (size_t)(k0 + k) * DH_ + nq);
            Bs[k][nq+0] = vv.x; Bs[k][nq+1] = vv.y;
            Bs[k][nq+2] = vv.z; Bs[k][nq+3] = vv.w;
        }
        __syncthreads();
        #pragma unroll
        for (int k = 0; k < BK; k++) {
            float a[TM], bb[TN];
            float4 a0 = *(const float4*)&As[k][ty*TM];
            a[0]=a0.x; a[1]=a0.y; a[2]=a0.z; a[3]=a0.w;
            float4 b0 = *(const float4*)&Bs[k][tx*TN];
            bb[0]=b0.x; bb[1]=b0.y; bb[2]=b0.z; bb[3]=b0.w;
            #pragma unroll
            for (int u = 0; u < TM; u++)
                #pragma unroll
                for (int w = 0; w < TN; w++) acc[u][w] += a[u] * bb[w];
        }
        __syncthreads();
    }

    #pragma unroll
    for (int u = 0; u < TM; u++) {
        int i = m0 + ty * TM + u;
        #pragma unroll
        for (int w = 0; w < TN; w++) {
            int d = tx * TN + w;
            g_att[((size_t)b * S_ + i) * D_ + h * DH_ + d] = acc[u][w];
        }
    }
}

// ==================================================================================
extern "C" void kernel_launch(void* const* d_in, const int* in_sizes, int n_in,
                              void* d_out, int out_size)
{
    const float* q      = (const float*)d_in[0];
    const float* k      = (const float*)d_in[1];
    const float* v      = (const float*)d_in[2];
    const float* pdiff  = (const float*)d_in[3];
    const float* Wk     = (const float*)d_in[4];
    const float* bk     = (const float*)d_in[5];
    const float* Wv     = (const float*)d_in[6];
    const float* bv     = (const float*)d_in[7];
    const float* Wo     = (const float*)d_in[8];
    const float* bo     = (const float*)d_in[9];
    const float* gammas = (const float*)d_in[10];
    float* out = (float*)d_out;

    float *qh, *kh, *vh, *att;
    cudaGetSymbolAddress((void**)&qh,  g_qh);
    cudaGetSymbolAddress((void**)&kh,  g_kh);
    cudaGetSymbolAddress((void**)&vh,  g_vh);
    cudaGetSymbolAddress((void**)&att, g_att);

    dim3 gg(D_ / 128, (B_ * S_) / 128);   // (8, 32)

    gemm_mma<true><<<gg, 256>>>(q, Wk, bk, qh);
    gemm_mma<true><<<gg, 256>>>(k, Wk, bk, kh);
    gemm_mma<true><<<gg, 256>>>(v, Wv, bv, vh);

    dv_kernel<<<(B_ * S_ * S_) / 256, 256>>>(pdiff);

    scores_kernel<<<dim3(8, 8, BH_), 256>>>();

    row_kernel<<<dim3(S_ / 8, BH_), 256>>>(gammas);

    pv_kernel<<<dim3(1, 8, BH_), 256>>>();

    gemm_mma<false><<<gg, 256>>>(att, Wo, bo, out);
}

// round 4
// speedup vs baseline: 2.9210x; 1.1505x over previous
#include <cuda_runtime.h>
#include <cuda_bf16.h>
#include <math.h>
#include <stdint.h>

#define B_  8
#define S_  512
#define D_  1024
#define H_  16
#define DH_ 64
#define BH_ 128

// ---------------- scratch (device globals; no runtime allocation) ----------------
__device__ float g_sc [(size_t)BH_*S_*S_];            // fp32 scores
__device__ float g_att[(size_t)B_*S_*D_];             // attention out, concat [B,S,D]
__device__ float g_dv [(size_t)B_*S_*S_];             // exp(sigmoid(pdiff))
__device__ __nv_bfloat16 g_qhh[(size_t)BH_*S_*DH_], g_qhl[(size_t)BH_*S_*DH_];
__device__ __nv_bfloat16 g_khh[(size_t)BH_*S_*DH_], g_khl[(size_t)BH_*S_*DH_];
__device__ __nv_bfloat16 g_vhh[(size_t)BH_*S_*DH_], g_vhl[(size_t)BH_*S_*DH_];
__device__ __nv_bfloat16 g_phi[(size_t)BH_*S_*S_],  g_plo[(size_t)BH_*S_*S_];

// ======================= warp-level bf16 MMA ======================================
__device__ __forceinline__ void mma_bf16(float* c, uint32_t a0, uint32_t a1,
                                         uint32_t a2, uint32_t a3,
                                         uint32_t b0, uint32_t b1) {
    asm volatile(
        "mma.sync.aligned.m16n8k16.row.col.f32.bf16.bf16.f32 "
        "{%0,%1,%2,%3}, {%4,%5,%6,%7}, {%8,%9}, {%0,%1,%2,%3};"
        : "+f"(c[0]), "+f"(c[1]), "+f"(c[2]), "+f"(c[3])
        : "r"(a0), "r"(a1), "r"(a2), "r"(a3), "r"(b0), "r"(b1));
}
__device__ __forceinline__ uint32_t pack_bf16(float x, float y) {
    __nv_bfloat162 t = __floats2bfloat162_rn(x, y);
    return *(uint32_t*)&t;
}
__device__ __forceinline__ void split4(float4 v, uint32_t& h0, uint32_t& h1,
                                       uint32_t& l0, uint32_t& l1) {
    h0 = pack_bf16(v.x, v.y);
    h1 = pack_bf16(v.z, v.w);
    __nv_bfloat162 hh0 = *(__nv_bfloat162*)&h0;
    __nv_bfloat162 hh1 = *(__nv_bfloat162*)&h1;
    l0 = pack_bf16(v.x - __bfloat162float(hh0.x), v.y - __bfloat162float(hh0.y));
    l1 = pack_bf16(v.z - __bfloat162float(hh1.x), v.w - __bfloat162float(hh1.y));
}

// ==================================================================================
// Double-buffered bf16x3 GEMM body:  C = A[M,K] * W[N,K]^T + bias
// Block 128x128, BK=32, 8 warps (2x4), warp tile 64x32, PAD 20 words.
// dsm layout: stage s at s*10240 words: {Ah:0, Al:2560, Bh:5120, Bl:7680}
// ==================================================================================
#define PADW 20
#define STG  10240

template<bool PAIR>
__device__ __forceinline__ void gemm_body(const float* __restrict__ A,
                                          const float* __restrict__ W,
                                          const float* __restrict__ bias,
                                          float* outF, __nv_bfloat16* outH,
                                          __nv_bfloat16* outL,
                                          int m0, int n0, uint32_t* dsm)
{
    int tid = threadIdx.x, lane = tid & 31, wid = tid >> 5;
    int wm = wid >> 2, wn = wid & 3;
    int lq = lane >> 2, tq = lane & 3;

    float acc[4][4][4];
    #pragma unroll
    for (int mt = 0; mt < 4; mt++)
        #pragma unroll
        for (int nt = 0; nt < 4; nt++)
            #pragma unroll
            for (int e = 0; e < 4; e++) acc[mt][nt][e] = 0.f;

    int rowr[4], cqr[4], wofs[4];
    #pragma unroll
    for (int r = 0; r < 4; r++) {
        int g = tid + r * 256;
        rowr[r] = g >> 3;
        cqr[r]  = g & 7;
        wofs[r] = rowr[r] * PADW + cqr[r] * 2;
    }

    float4 va[4], vb[4];
    #pragma unroll
    for (int r = 0; r < 4; r++) {
        va[r] = *(const float4*)(A + (size_t)(m0 + rowr[r]) * D_ + cqr[r] * 4);
        vb[r] = *(const float4*)(W + (size_t)(n0 + rowr[r]) * D_ + cqr[r] * 4);
    }

    auto cvtstore = [&](uint32_t* base) {
        #pragma unroll
        for (int r = 0; r < 4; r++) {
            uint32_t h0, h1, l0, l1;
            split4(va[r], h0, h1, l0, l1);
            base[wofs[r]]        = h0; base[wofs[r] + 1]        = h1;
            base[2560 + wofs[r]] = l0; base[2560 + wofs[r] + 1] = l1;
            split4(vb[r], h0, h1, l0, l1);
            base[5120 + wofs[r]] = h0; base[5120 + wofs[r] + 1] = h1;
            base[7680 + wofs[r]] = l0; base[7680 + wofs[r] + 1] = l1;
        }
    };

    cvtstore(dsm);          // stage 0 <- chunk 0
    int stage = 0;

    for (int kc = 0; kc < 32; kc++) {
        __syncthreads();
        if (kc < 31) {
            int k0 = (kc + 1) * 32;
            #pragma unroll
            for (int r = 0; r < 4; r++) {
                va[r] = *(const float4*)(A + (size_t)(m0 + rowr[r]) * D_ + k0 + cqr[r] * 4);
                vb[r] = *(const float4*)(W + (size_t)(n0 + rowr[r]) * D_ + k0 + cqr[r] * 4);
            }
        }
        uint32_t* base = dsm + stage * STG;
        #pragma unroll
        for (int ks = 0; ks < 2; ks++) {
            int kofs = ks * 8 + tq;
            uint32_t bh[4][2], bl[4][2];
            #pragma unroll
            for (int nt = 0; nt < 4; nt++) {
                int bi = (wn * 32 + nt * 8 + lq) * PADW + kofs;
                bh[nt][0] = base[5120 + bi]; bh[nt][1] = base[5120 + bi + 4];
                bl[nt][0] = base[7680 + bi]; bl[nt][1] = base[7680 + bi + 4];
            }
            #pragma unroll
            for (int mt = 0; mt < 4; mt++) {
                int ai = (wm * 64 + mt * 16 + lq) * PADW + kofs;
                uint32_t ah0 = base[ai],            ah1 = base[ai + 8 * PADW];
                uint32_t ah2 = base[ai + 4],        ah3 = base[ai + 8 * PADW + 4];
                uint32_t al0 = base[2560 + ai],     al1 = base[2560 + ai + 8 * PADW];
                uint32_t al2 = base[2560 + ai + 4], al3 = base[2560 + ai + 8 * PADW + 4];
                #pragma unroll
                for (int nt = 0; nt < 4; nt++) {
                    mma_bf16(acc[mt][nt], ah0, ah1, ah2, ah3, bh[nt][0], bh[nt][1]);
                    mma_bf16(acc[mt][nt], ah0, ah1, ah2, ah3, bl[nt][0], bl[nt][1]);
                    mma_bf16(acc[mt][nt], al0, al1, al2, al3, bh[nt][0], bh[nt][1]);
                }
            }
        }
        if (kc < 31) cvtstore(dsm + (stage ^ 1) * STG);
        stage ^= 1;
    }

    // ---- epilogue ----
    #pragma unroll
    for (int mt = 0; mt < 4; mt++) {
        #pragma unroll
        for (int nt = 0; nt < 4; nt++) {
            int n = n0 + wn * 32 + nt * 8 + tq * 2;
            float b0v = __ldg(bias + n), b1v = __ldg(bias + n + 1);
            #pragma unroll
            for (int hf = 0; hf < 2; hf++) {
                int m = m0 + wm * 64 + mt * 16 + lq + hf * 8;
                float v0 = acc[mt][nt][hf * 2 + 0] + b0v;
                float v1 = acc[mt][nt][hf * 2 + 1] + b1v;
                if (PAIR) {
                    int bb = m / S_, srow = m % S_;
                    int h = n >> 6, d = n & 63;
                    size_t idx = (((size_t)bb * H_ + h) * S_ + srow) * DH_ + d;
                    __nv_bfloat16 h0 = __float2bfloat16(v0);
                    __nv_bfloat16 h1 = __float2bfloat16(v1);
                    __nv_bfloat162 hv; hv.x = h0; hv.y = h1;
                    __nv_bfloat162 lv;
                    lv.x = __float2bfloat16(v0 - __bfloat162float(h0));
                    lv.y = __float2bfloat16(v1 - __bfloat162float(h1));
                    *(__nv_bfloat162*)(outH + idx) = hv;
                    *(__nv_bfloat162*)(outL + idx) = lv;
                } else {
                    *(float2*)&outF[(size_t)m * D_ + n] = make_float2(v0, v1);
                }
            }
        }
    }
}

__global__ __launch_bounds__(256, 1)
void gemm_qkv(const float* __restrict__ q, const float* __restrict__ k,
              const float* __restrict__ v, const float* __restrict__ Wk,
              const float* __restrict__ bk, const float* __restrict__ Wv,
              const float* __restrict__ bv)
{
    extern __shared__ __align__(16) uint32_t dsm[];
    int z = blockIdx.z;
    const float* A    = (z == 0) ? q : (z == 1) ? k : v;
    const float* W    = (z == 2) ? Wv : Wk;
    const float* bias = (z == 2) ? bv : bk;
    __nv_bfloat16* oh = (z == 0) ? g_qhh : (z == 1) ? g_khh : g_vhh;
    __nv_bfloat16* ol = (z == 0) ? g_qhl : (z == 1) ? g_khl : g_vhl;
    gemm_body<true>(A, W, bias, nullptr, oh, ol,
                    blockIdx.y * 128, blockIdx.x * 128, dsm);
}

__global__ __launch_bounds__(256, 1)
void gemm_out(const float* __restrict__ A, const float* __restrict__ W,
              const float* __restrict__ bias, float* __restrict__ out)
{
    extern __shared__ __align__(16) uint32_t dsm[];
    gemm_body<false>(A, W, bias, out, nullptr, nullptr,
                     blockIdx.y * 128, blockIdx.x * 128, dsm);
}

// ==================================================================================
// Scores via MMA: per head z, tile 128x128, causal (10 of 16 tiles).
// K=64 loaded once into SMEM (PAD 36 words). 3 hi/lo passes.
// ==================================================================================
#define PADS 36

__global__ __launch_bounds__(256, 1)
void scores_mma()
{
    extern __shared__ __align__(16) uint32_t sm[];
    uint32_t* sQh = sm;
    uint32_t* sQl = sm + 4608;
    uint32_t* sKh = sm + 9216;
    uint32_t* sKl = sm + 13824;

    int z = blockIdx.y;
    int t = blockIdx.x;
    int mi = (t < 1) ? 0 : (t < 3) ? 1 : (t < 6) ? 2 : 3;
    int ni = t - mi * (mi + 1) / 2;
    int m0 = mi * 128, n0 = ni * 128;

    int tid = threadIdx.x, lane = tid & 31, wid = tid >> 5;
    int wm = wid >> 2, wn = wid & 3, lq = lane >> 2, tq = lane & 3;

    const uint32_t* qh = (const uint32_t*)(g_qhh + (size_t)z * S_ * DH_);
    const uint32_t* ql = (const uint32_t*)(g_qhl + (size_t)z * S_ * DH_);
    const uint32_t* kh = (const uint32_t*)(g_khh + (size_t)z * S_ * DH_);
    const uint32_t* kl = (const uint32_t*)(g_khl + (size_t)z * S_ * DH_);

    // load tiles: row = tid>>1 (0..127), hf = tid&1 selects 16-word half
    {
        int row = tid >> 1, hf = tid & 1;
        int gq = (m0 + row) * 32 + hf * 16;
        int gk = (n0 + row) * 32 + hf * 16;
        int so = row * PADS + hf * 16;
        #pragma unroll
        for (int qd = 0; qd < 4; qd++) {
            uint4 v0 = *(const uint4*)(qh + gq + qd * 4);
            uint4 v1 = *(const uint4*)(ql + gq + qd * 4);
            uint4 v2 = *(const uint4*)(kh + gk + qd * 4);
            uint4 v3 = *(const uint4*)(kl + gk + qd * 4);
            uint2* p;
            p = (uint2*)(sQh + so + qd * 4); p[0] = make_uint2(v0.x, v0.y); p[1] = make_uint2(v0.z, v0.w);
            p = (uint2*)(sQl + so + qd * 4); p[0] = make_uint2(v1.x, v1.y); p[1] = make_uint2(v1.z, v1.w);
            p = (uint2*)(sKh + so + qd * 4); p[0] = make_uint2(v2.x, v2.y); p[1] = make_uint2(v2.z, v2.w);
            p = (uint2*)(sKl + so + qd * 4); p[0] = make_uint2(v3.x, v3.y); p[1] = make_uint2(v3.z, v3.w);
        }
    }
    __syncthreads();

    float acc[4][4][4];
    #pragma unroll
    for (int mt = 0; mt < 4; mt++)
        #pragma unroll
        for (int nt = 0; nt < 4; nt++)
            #pragma unroll
            for (int e = 0; e < 4; e++) acc[mt][nt][e] = 0.f;

    #pragma unroll
    for (int ks = 0; ks < 4; ks++) {
        int kofs = ks * 8 + tq;
        uint32_t bh[4][2], bl[4][2];
        #pragma unroll
        for (int nt = 0; nt < 4; nt++) {
            int bi = (wn * 32 + nt * 8 + lq) * PADS + kofs;
            bh[nt][0] = sKh[bi]; bh[nt][1] = sKh[bi + 4];
            bl[nt][0] = sKl[bi]; bl[nt][1] = sKl[bi + 4];
        }
        #pragma unroll
        for (int mt = 0; mt < 4; mt++) {
            int ai = (wm * 64 + mt * 16 + lq) * PADS + kofs;
            uint32_t ah0 = sQh[ai],     ah1 = sQh[ai + 8 * PADS];
            uint32_t ah2 = sQh[ai + 4], ah3 = sQh[ai + 8 * PADS + 4];
            uint32_t al0 = sQl[ai],     al1 = sQl[ai + 8 * PADS];
            uint32_t al2 = sQl[ai + 4], al3 = sQl[ai + 8 * PADS + 4];
            #pragma unroll
            for (int nt = 0; nt < 4; nt++) {
                mma_bf16(acc[mt][nt], ah0, ah1, ah2, ah3, bh[nt][0], bh[nt][1]);
                mma_bf16(acc[mt][nt], ah0, ah1, ah2, ah3, bl[nt][0], bl[nt][1]);
                mma_bf16(acc[mt][nt], al0, al1, al2, al3, bh[nt][0], bh[nt][1]);
            }
        }
    }

    float* C = g_sc + (size_t)z * S_ * S_;
    #pragma unroll
    for (int mt = 0; mt < 4; mt++) {
        #pragma unroll
        for (int nt = 0; nt < 4; nt++) {
            int j = n0 + wn * 32 + nt * 8 + tq * 2;
            #pragma unroll
            for (int hf = 0; hf < 2; hf++) {
                int i = m0 + wm * 64 + mt * 16 + lq + hf * 8;
                *(float2*)&C[(size_t)i * S_ + j] =
                    make_float2(acc[mt][nt][hf * 2] * 0.125f,
                                acc[mt][nt][hf * 2 + 1] * 0.125f);
            }
        }
    }
}

// ==================================================================================
// dv precompute
// ==================================================================================
__global__ __launch_bounds__(256)
void dv_kernel(const float* __restrict__ pdiff)
{
    size_t idx = (size_t)blockIdx.x * 256 + threadIdx.x;
    float x = pdiff[idx];
    float sig = 1.f / (1.f + __expf(-x));
    g_dv[idx] = __expf(sig);
}

// ==================================================================================
// Row kernel: warp per row; writes P as bf16 hi/lo (zero-padded to 128-boundary)
// ==================================================================================
__global__ __launch_bounds__(256)
void row_kernel(const float* __restrict__ gammas)
{
    int warp = threadIdx.x >> 5, lane = threadIdx.x & 31;
    int i = blockIdx.x * 8 + warp;
    int z = blockIdx.y;
    int b = z >> 4, h = z & 15;

    const float* row   = g_sc + ((size_t)z * S_ + i) * S_;
    const float* dvrow = g_dv + ((size_t)b * S_ + i) * S_;

    int nch = (i >> 5) + 1;
    float scv[16], s2v[16];

    float mx = -3.0e38f;
    #pragma unroll
    for (int c = 0; c < 16; c++) {
        if (c < nch) {
            int j = c * 32 + lane;
            float v = row[j];
            scv[c] = v;
            if (j <= i) mx = fmaxf(mx, v);
        }
    }
    #pragma unroll
    for (int o = 16; o > 0; o >>= 1) mx = fmaxf(mx, __shfl_xor_sync(0xFFFFFFFFu, mx, o));

    float run = 0.f;
    #pragma unroll
    for (int c = 0; c < 16; c++) {
        if (c < nch) {
            int j = c * 32 + lane;
            float p = (j <= i) ? __expf(scv[c] - mx) : 0.f;
            float s = p;
            #pragma unroll
            for (int d = 1; d < 32; d <<= 1) {
                float tt = __shfl_up_sync(0xFFFFFFFFu, s, d);
                if (lane >= d) s += tt;
            }
            s2v[c] = run + s;
            run += __shfl_sync(0xFFFFFFFFu, s, 31);
        }
    }
    float tot  = run;
    float rtot = 1.f / fmaxf(tot, 1e-30f);

    float g = gammas[h];
    float gamma = -log1pf(__expf(g));

    float mx2 = -3.0e38f;
    #pragma unroll
    for (int c = 0; c < 16; c++) {
        if (c < nch) {
            int j = c * 32 + lane;
            float rem  = fmaxf(tot - s2v[c], 0.f) * rtot;
            float pos  = (float)(i - j);
            float dist = sqrtf(fmaxf(rem * pos, 0.f));
            float dv   = dvrow[j];
            float eff  = __expf(dist * gamma * dv);
            eff = fminf(fmaxf(eff, 1e-5f), 1e5f);
            float s2 = scv[c] * eff;
            s2v[c] = s2;
            if (j <= i) mx2 = fmaxf(mx2, s2);
        }
    }
    #pragma unroll
    for (int o = 16; o > 0; o >>= 1) mx2 = fmaxf(mx2, __shfl_xor_sync(0xFFFFFFFFu, mx2, o));

    float sum2 = 0.f;
    #pragma unroll
    for (int c = 0; c < 16; c++) {
        if (c < nch) {
            int j = c * 32 + lane;
            float e2 = (j <= i) ? __expf(s2v[c] - mx2) : 0.f;
            s2v[c] = e2;
            sum2 += e2;
        }
    }
    #pragma unroll
    for (int o = 16; o > 0; o >>= 1) sum2 += __shfl_xor_sync(0xFFFFFFFFu, sum2, o);

    float rs = (i == 0) ? 0.f : 1.f / sum2;

    __nv_bfloat16* ph = g_phi + ((size_t)z * S_ + i) * S_;
    __nv_bfloat16* pl = g_plo + ((size_t)z * S_ + i) * S_;
    int nwrite = ((i >> 7) + 1) * 4;   // zero-fill to 128-boundary for PV tiles
    #pragma unroll
    for (int c = 0; c < 16; c++) {
        int j = c * 32 + lane;
        if (c < nch || c < nwrite) {
            float p = (c < nch && j <= i) ? s2v[c] * rs : 0.f;
            __nv_bfloat16 hh = __float2bfloat16(p);
            ph[j] = hh;
            pl[j] = __float2bfloat16(p - __bfloat162float(hh));
        }
    }
}

// ==================================================================================
// PV via MMA: out[i,d] = sum_j P[i,j] V[j,d].  Block 128(M) x 64(N=DH).
// A = P hi/lo (K contiguous); B = V transposed in SMEM during load.
// ==================================================================================
__global__ __launch_bounds__(256, 1)
void pv_mma()
{
    extern __shared__ __align__(16) uint32_t sm[];
    uint32_t* sPh = sm;
    uint32_t* sPl = sm + 4608;
    uint32_t* sVh = sm + 9216;
    uint32_t* sVl = sm + 11520;
    __nv_bfloat16* sVh16 = (__nv_bfloat16*)sVh;
    __nv_bfloat16* sVl16 = (__nv_bfloat16*)sVl;

    int z  = blockIdx.y;
    int b  = z >> 4, h = z & 15;
    int m0 = (3 - (int)blockIdx.x) * 128;   // heavy tiles first

    int tid = threadIdx.x, lane = tid & 31, wid = tid >> 5;
    int wm = wid >> 2, wn = wid & 3, lq = lane >> 2, tq = lane & 3;

    const uint32_t* pwh = (const uint32_t*)(g_phi + (size_t)z * S_ * S_);
    const uint32_t* pwl = (const uint32_t*)(g_plo + (size_t)z * S_ * S_);
    const uint32_t* vwh = (const uint32_t*)(g_vhh + (size_t)z * S_ * DH_);
    const uint32_t* vwl = (const uint32_t*)(g_vhl + (size_t)z * S_ * DH_);

    float acc[4][2][4];
    #pragma unroll
    for (int mt = 0; mt < 4; mt++)
        #pragma unroll
        for (int nt = 0; nt < 2; nt++)
            #pragma unroll
            for (int e = 0; e < 4; e++) acc[mt][nt][e] = 0.f;

    int nchunks = m0 / 64 + 2;

    for (int c = 0; c < nchunks; c++) {
        int k0 = c * 64;
        // ---- load P chunk (128 rows x 32 words) ----
        {
            int row = tid >> 1, hf = tid & 1;
            int gofs = (m0 + row) * 256 + k0 / 2 + hf * 16;
            int so = row * PADS + hf * 16;
            #pragma unroll
            for (int qd = 0; qd < 4; qd++) {
                uint4 v0 = *(const uint4*)(pwh + gofs + qd * 4);
                uint4 v1 = *(const uint4*)(pwl + gofs + qd * 4);
                uint2* p;
                p = (uint2*)(sPh + so + qd * 4); p[0] = make_uint2(v0.x, v0.y); p[1] = make_uint2(v0.z, v0.w);
                p = (uint2*)(sPl + so + qd * 4); p[0] = make_uint2(v1.x, v1.y); p[1] = make_uint2(v1.z, v1.w);
            }
        }
        // ---- load V chunk transposed: sV[d][k_local], pitch 36 words = 72 bf16 ----
        {
            int r  = tid >> 2;              // 0..63 (k_local)
            int w0 = (tid & 3) * 8;         // word start (d pairs)
            #pragma unroll
            for (int qd = 0; qd < 2; qd++) {
                uint4 vv = *(const uint4*)(vwh + (k0 + r) * 32 + w0 + qd * 4);
                uint32_t wv[4] = {vv.x, vv.y, vv.z, vv.w};
                #pragma unroll
                for (int q2 = 0; q2 < 4; q2++) {
                    int d0 = (w0 + qd * 4 + q2) * 2;
                    __nv_bfloat162 pr = *(__nv_bfloat162*)&wv[q2];
                    sVh16[d0 * 72 + r]       = pr.x;
                    sVh16[(d0 + 1) * 72 + r] = pr.y;
                }
                vv = *(const uint4*)(vwl + (k0 + r) * 32 + w0 + qd * 4);
                wv[0] = vv.x; wv[1] = vv.y; wv[2] = vv.z; wv[3] = vv.w;
                #pragma unroll
                for (int q2 = 0; q2 < 4; q2++) {
                    int d0 = (w0 + qd * 4 + q2) * 2;
                    __nv_bfloat162 pr = *(__nv_bfloat162*)&wv[q2];
                    sVl16[d0 * 72 + r]       = pr.x;
                    sVl16[(d0 + 1) * 72 + r] = pr.y;
                }
            }
        }
        __syncthreads();

        #pragma unroll
        for (int ks = 0; ks < 4; ks++) {
            int kofs = ks * 8 + tq;
            uint32_t bh[2][2], bl[2][2];
            #pragma unroll
            for (int nt = 0; nt < 2; nt++) {
                int bi = (wn * 16 + nt * 8 + lq) * PADS + kofs;
                bh[nt][0] = sVh[bi]; bh[nt][1] = sVh[bi + 4];
                bl[nt][0] = sVl[bi]; bl[nt][1] = sVl[bi + 4];
            }
            #pragma unroll
            for (int mt = 0; mt < 4; mt++) {
                int ai = (wm * 64 + mt * 16 + lq) * PADS + kofs;
                uint32_t ah0 = sPh[ai],     ah1 = sPh[ai + 8 * PADS];
                uint32_t ah2 = sPh[ai + 4], ah3 = sPh[ai + 8 * PADS + 4];
                uint32_t al0 = sPl[ai],     al1 = sPl[ai + 8 * PADS];
                uint32_t al2 = sPl[ai + 4], al3 = sPl[ai + 8 * PADS + 4];
                #pragma unroll
                for (int nt = 0; nt < 2; nt++) {
                    mma_bf16(acc[mt][nt], ah0, ah1, ah2, ah3, bh[nt][0], bh[nt][1]);
                    mma_bf16(acc[mt][nt], al0, al1, al2, al3, bh[nt][0], bh[nt][1]);
                    mma_bf16(acc[mt][nt], ah0, ah1, ah2, ah3, bl[nt][0], bl[nt][1]);
                }
            }
        }
        __syncthreads();
    }

    #pragma unroll
    for (int mt = 0; mt < 4; mt++) {
        #pragma unroll
        for (int nt = 0; nt < 2; nt++) {
            int d = wn * 16 + nt * 8 + tq * 2;
            #pragma unroll
            for (int hf = 0; hf < 2; hf++) {
                int i = m0 + wm * 64 + mt * 16 + lq + hf * 8;
                *(float2*)&g_att[((size_t)b * S_ + i) * D_ + h * DH_ + d] =
                    make_float2(acc[mt][nt][hf * 2], acc[mt][nt][hf * 2 + 1]);
            }
        }
    }
}

// ==================================================================================
extern "C" void kernel_launch(void* const* d_in, const int* in_sizes, int n_in,
                              void* d_out, int out_size)
{
    const float* q      = (const float*)d_in[0];
    const float* k      = (const float*)d_in[1];
    const float* v      = (const float*)d_in[2];
    const float* pdiff  = (const float*)d_in[3];
    const float* Wk     = (const float*)d_in[4];
    const float* bk     = (const float*)d_in[5];
    const float* Wv     = (const float*)d_in[6];
    const float* bv     = (const float*)d_in[7];
    const float* Wo     = (const float*)d_in[8];
    const float* bo     = (const float*)d_in[9];
    const float* gammas = (const float*)d_in[10];
    float* out = (float*)d_out;

    float* att;
    cudaGetSymbolAddress((void**)&att, g_att);

    cudaFuncSetAttribute(gemm_qkv,   cudaFuncAttributeMaxDynamicSharedMemorySize, 81920);
    cudaFuncSetAttribute(gemm_out,   cudaFuncAttributeMaxDynamicSharedMemorySize, 81920);
    cudaFuncSetAttribute(scores_mma, cudaFuncAttributeMaxDynamicSharedMemorySize, 73728);
    cudaFuncSetAttribute(pv_mma,     cudaFuncAttributeMaxDynamicSharedMemorySize, 55296);

    gemm_qkv<<<dim3(8, 32, 3), 256, 81920>>>(q, k, v, Wk, bk, Wv, bv);

    dv_kernel<<<(B_ * S_ * S_) / 256, 256>>>(pdiff);

    scores_mma<<<dim3(10, BH_), 256, 73728>>>();

    row_kernel<<<dim3(S_ / 8, BH_), 256>>>(gammas);

    pv_mma<<<dim3(4, BH_), 256, 55296>>>();

    gemm_out<<<dim3(8, 32), 256, 81920>>>(att, Wo, bo, out);
}